// round 15
// baseline (speedup 1.0000x reference)
#include <cuda_runtime.h>

// Problem constants
#define Kc    9
#define NCc   13
#define NAc   5
#define NBc   128
#define NHc   26
#define NWc   26
#define NTc   50
#define Lc    21          // 2K+3
#define NPIX  (NHc*NWc)   // 676
#define NANCH (NAc*NHc*NWc) // 3380
#define CH    (2*Kc+1+NCc) // 32
#define NBMW  106          // ceil(3380/32)

#define THf     80.0f
#define TH2f    6400.0f
#define SILf    0.6f
#define OBJf    5.0f
// 1/(exp(2)-1)
#define INVC0   0.15651764274966574f

#define SXc (640.0f/26.0f)
#define SYc (480.0f/26.0f)

typedef unsigned long long ull;
typedef unsigned int uint;

// Scratch (device globals — no allocation allowed)
// Per (b,t): 20 floats = 5 float4; group g in 0..3 (corner pair 2g,2g+1):
//   [g*4+0]=-gx_{2g}  [g*4+1]=-gx_{2g+1}  [g*4+2]=-gy_{2g}  [g*4+3]=-gy_{2g+1}
// [16]=-gx8 [17]=-gy8 [18]=pad [19]=pad
__device__ __align__(16) float d_gtn[NBc*NTc*20];
__device__ float d_txv[NBc*NTc*Kc];
__device__ float d_tyv[NBc*NTc*Kc];
__device__ float d_conft[NBc*NTc];
__device__ float d_tclsA[NBc*NTc];
__device__ int   d_codeA[NBc*NTc];
__device__ int   d_nvalid[NBc];

__constant__ float c_anch[10] = {1.482f,2.2412f,2.0501f,3.1265f,2.3946f,
                                 4.6891f,3.1018f,3.991f,3.4879f,5.8851f};

__device__ __forceinline__ float sigmoidf_(float x) { return 1.0f/(1.0f+expf(-x)); }

__device__ __forceinline__ ull pack2(float lo, float hi) {
    ull r;
    asm("mov.b64 %0, {%1, %2};" : "=l"(r) : "f"(lo), "f"(hi));
    return r;
}
__device__ __forceinline__ ull fma2_(ull a, ull b, ull c) {
    ull d;
    asm("fma.rn.f32x2 %0, %1, %2, %3;" : "=l"(d) : "l"(a), "l"(b), "l"(c));
    return d;
}
__device__ __forceinline__ ull add2_(ull a, ull b) {
    ull d;
    asm("add.rn.f32x2 %0, %1, %2;" : "=l"(d) : "l"(a), "l"(b));
    return d;
}
// d^2 - TH^2 for a corner pair (direct form)
__device__ __forceinline__ ull dist2m(ull px, ull py, ull ngx, ull ngy, ull nTH2) {
    ull dx = add2_(px, ngx);
    ull dy = add2_(py, ngy);
    return fma2_(dx, dx, fma2_(dy, dy, nTH2));
}
// sign bytes of 4 packed floats (two ulls) -> bytes 0..3 as 0xFF/0x00
__device__ __forceinline__ uint prmt_sgn4(ull a, ull b) {
    uint r;
    asm("{\n\t"
        ".reg .b32 alo, ahi, blo, bhi, t0, t1;\n\t"
        "mov.b64 {alo, ahi}, %1;\n\t"
        "mov.b64 {blo, bhi}, %2;\n\t"
        "prmt.b32 t0, alo, ahi, 0x000000FB;\n\t"
        "prmt.b32 t1, blo, bhi, 0x0000FB00;\n\t"
        "or.b32 %0, t0, t1;\n\t"
        "}" : "=r"(r) : "l"(a), "l"(b));
    return r;
}
// sign bytes of the two packed floats in d -> bytes 0,1 as 0xFF/0x00
__device__ __forceinline__ uint prmt_sgn(ull d) {
    uint lo = (uint)d, hi = (uint)(d >> 32), r;
    asm("prmt.b32 %0, %1, %2, 0x000000FB;" : "=r"(r) : "r"(lo), "r"(hi));
    return r;
}
// acc += dot(sign bytes, sel)  (-1 per inside corner among selected bytes)
__device__ __forceinline__ int dp4a_sel(uint s, uint sel, int acc) {
    int r;
    asm("dp4a.s32.s32 %0, %1, %2, %3;" : "=r"(r) : "r"(s), "r"(sel), "r"(acc));
    return r;
}

// One block per batch; thread t handles target t. Also zeroes the loss scalar.
__global__ void region_prep(const float* __restrict__ out,
                            const float* __restrict__ tgt,
                            float* __restrict__ loss)
{
    int b = blockIdx.x;
    int t = threadIdx.x;
    if (b == 0 && t == 0) loss[0] = 0.0f;

    __shared__ int sflag[NTc];
    if (t < NTc)
        sflag[t] = (tgt[(size_t)b*NTc*Lc + (size_t)t*Lc + 1] != 0.0f) ? 1 : 0;
    __syncthreads();
    if (t == 0) {
        int nv = NTc;
        for (int q = 0; q < NTc; ++q) if (!sflag[q]) { nv = q; break; }
        d_nvalid[b] = nv;
    }
    if (t >= NTc) return;

    const float* row = tgt + (size_t)b*NTc*Lc + (size_t)t*Lc;
    float gxr[Kc], gyr[Kc];
#pragma unroll
    for (int k = 0; k < Kc; ++k) { gxr[k] = row[1+2*k]; gyr[k] = row[2+2*k]; }

    int gi0 = (int)floorf(gxr[0]*(float)NWc);
    int gj0 = (int)floorf(gyr[0]*(float)NHc);
    gi0 = min(max(gi0, 0), NWc-1);
    gj0 = min(max(gj0, 0), NHc-1);

    int idx = b*NTc + t;

    float gpx[Kc], gpy[Kc];
#pragma unroll
    for (int k = 0; k < Kc; ++k) {
        gpx[k] = gxr[k]*640.0f;
        gpy[k] = gyr[k]*480.0f;
        d_txv[idx*Kc+k] = gxr[k]*(float)NWc - (float)gi0;
        d_tyv[idx*Kc+k] = gyr[k]*(float)NHc - (float)gj0;
    }
    float* gt = &d_gtn[idx*20];
#pragma unroll
    for (int g = 0; g < 4; ++g) {
        gt[g*4+0] = -gpx[2*g];  gt[g*4+1] = -gpx[2*g+1];
        gt[g*4+2] = -gpy[2*g];  gt[g*4+3] = -gpy[2*g+1];
    }
    gt[16] = -gpx[8]; gt[17] = -gpy[8]; gt[18] = 0.0f; gt[19] = 0.0f;

    // best anchor by IoU on (gw, gh); first max wins (strict >)
    float gw = row[Lc-2]*(float)NWc;
    float gh = row[Lc-1]*(float)NHc;
    float best = -1.0f; int bn = 0;
#pragma unroll
    for (int a = 0; a < NAc; ++a) {
        float aw = c_anch[2*a], ah = c_anch[2*a+1];
        float mw = fminf(aw, gw), mh = fminf(ah, gh);
        float inter = mw*mh;
        float iou = inter / (aw*ah + gw*gh - inter);
        if (iou > best) { best = iou; bn = a; }
    }
    d_codeA[idx] = bn*NPIX + gj0*NWc + gi0;
    d_tclsA[idx] = row[0];

    // conf_t: gather pred box from batch (b-1 mod NB), anchor NA-1, cell (gj0, gi0)
    int bp = (b + NBc - 1) % NBc;
    const float* cb = out + ((size_t)(bp*NAc + (NAc-1))*CH)*NPIX
                          + (size_t)(gj0*NWc + gi0);
    float acc = 0.0f;
#pragma unroll
    for (int k = 0; k < Kc; ++k) {
        float xv = cb[(2*k)*NPIX];
        float yv = cb[(2*k+1)*NPIX];
        if (k == 0) { xv = sigmoidf_(xv); yv = sigmoidf_(yv); }
        float px = (xv + (float)gi0) * (1.0f/(float)NWc);
        float py = (yv + (float)gj0) * (1.0f/(float)NHc);
        float dx = (px - gxr[k]) * 640.0f;
        float dy = (py - gyr[k]) * 480.0f;
        float d2 = fmaf(dx, dx, dy*dy);
        if (d2 < TH2f) {
            float d = sqrtf(d2);
            acc += (expf(2.0f - d*0.025f) - 1.0f) * INVC0;
        }
    }
    d_conft[idx] = acc * (1.0f/(float)Kc);
}

// COLD: full exact rescan of all targets for one cell. Decision logic
// identical to the screen/reference: count corners with d^2 < TH^2; if >= 6,
// exact corner-conf sum; max over targets.
__device__ __noinline__ float rescan_cell(const float* __restrict__ cb,
                                          const float* __restrict__ sgt,
                                          int cell, int nv)
{
    int a = cell / NPIX, pos = cell - a*NPIX;
    int jj = pos / NWc, ii = pos - jj*NWc;
    float fx = (float)ii * SXc, fy = (float)jj * SYc;
    float pxs[Kc], pys[Kc];
#pragma unroll
    for (int k = 0; k < Kc; ++k) {
        float xv = cb[(2*k)*NPIX];
        float yv = cb[(2*k+1)*NPIX];
        if (k == 0) { xv = sigmoidf_(xv); yv = sigmoidf_(yv); }
        pxs[k] = fmaf(xv, SXc, fx);
        pys[k] = fmaf(yv, SYc, fy);
    }
    float m = 0.0f;
    for (int t = 0; t < nv; ++t) {
        const float* tp = &sgt[t*20];
        int cnt = 0;
        float d2s[Kc];
#pragma unroll
        for (int k = 0; k < Kc; ++k) {
            float ngx = (k < 8) ? tp[(k>>1)*4 + (k&1)]     : tp[16];
            float ngy = (k < 8) ? tp[(k>>1)*4 + 2 + (k&1)] : tp[17];
            float dx = pxs[k] + ngx;
            float dy = pys[k] + ngy;
            float dd = fmaf(dx, dx, fmaf(dy, dy, -TH2f));
            d2s[k] = dd;
            cnt += (__float_as_uint(dd) >> 31);
        }
        if (cnt >= 6) {
            float acc = 0.0f;
#pragma unroll
            for (int k = 0; k < Kc; ++k) {
                if (d2s[k] < 0.0f) {
                    float d = sqrtf(d2s[k] + TH2f);
                    acc += (expf(2.0f - d*0.025f) - 1.0f) * INVC0;
                }
            }
            m = fmaxf(m, acc);
        }
    }
    return m;
}

// rare per-object-cell / noobj epilogue
__device__ __noinline__ float cell_loss(const float* __restrict__ cb,
                                        int b, int win, int doconf, int over_sil,
                                        const float* __restrict__ sconft,
                                        const float* __restrict__ stcls)
{
    float contrib = 0.0f;
    if (win >= 0) {
        const float* txp = &d_txv[(b*NTc + win)*Kc];
        const float* typ = &d_tyv[(b*NTc + win)*Kc];
        float cl = 0.0f;
#pragma unroll
        for (int k = 0; k < Kc; ++k) {
            float xv = cb[(2*k)*NPIX];
            float yv = cb[(2*k+1)*NPIX];
            if (k == 0) { xv = sigmoidf_(xv); yv = sigmoidf_(yv); }
            float exd = xv - txp[k];
            float eyd = yv - typ[k];
            cl += exd*exd + eyd*eyd;
        }
        contrib = 0.5f*cl;

        float lg[NCc];
        float mx = -1e30f;
#pragma unroll
        for (int c = 0; c < NCc; ++c) {
            lg[c] = cb[(2*Kc+1+c)*NPIX];
            mx = fmaxf(mx, lg[c]);
        }
        float se = 0.0f;
#pragma unroll
        for (int c = 0; c < NCc; ++c) se += expf(lg[c]-mx);
        int lab = (int)stcls[win];
        lab = min(max(lab, 0), NCc-1);
        contrib += (mx + logf(se)) - lg[lab];

        if (doconf) {
            float conf = sigmoidf_(cb[(2*Kc)*NPIX]);
            float dc = conf - sconft[win];
            contrib += 0.5f*OBJf*dc*dc;
        }
    } else {
        if (doconf && !over_sil) {
            float conf = sigmoidf_(cb[(2*Kc)*NPIX]);
            contrib += 0.5f*conf*conf;
        }
    }
    return contrib;
}

// grid: (14, NB) ; one thread per cell (256 cells per block)
__global__ __launch_bounds__(256, 4)
void region_main(const float* __restrict__ out,
                 const int*   __restrict__ ep,
                 float* __restrict__ loss)
{
    int b   = blockIdx.y;
    int tid = threadIdx.x;
    int cell = blockIdx.x*256 + tid;

    // one extra dummy target slot at index nv (coords 1e18 -> never inside)
    __shared__ __align__(16) float sgt[(NTc+1)*20];
    __shared__ float sconft[NTc], stcls[NTc];
    __shared__ int   scode[NTc];
    __shared__ uint  sbm[NBMW];
    __shared__ float wred[8];
    __shared__ int   snv;

    {
        const float4* src = (const float4*)&d_gtn[b*NTc*20];
        float4* dst = (float4*)sgt;
        for (int i2 = tid; i2 < NTc*20/4; i2 += 256) dst[i2] = src[i2];
    }
    if (tid < NBMW) sbm[tid] = 0u;
    if (tid == 0) snv = d_nvalid[b];
    if (tid < NTc) {
        sconft[tid] = d_conft[b*NTc + tid];
        stcls[tid]  = d_tclsA[b*NTc + tid];
        scode[tid]  = d_codeA[b*NTc + tid];
    }
    __syncthreads();      // bitmap fully zeroed + scode/snv visible
    if (tid < NTc && tid < snv) {
        int code = scode[tid];
        atomicOr(&sbm[code >> 5], 1u << (code & 31));
    }
    if (tid < 20) sgt[snv*20 + tid] = 1e18f;   // dummy pad target
    __syncthreads();

    int act = (cell < NANCH);

    // per-cell packed state: 4 pair groups + scalar corner 8
    ull px[4], py[4];
    float px8 = 60000.0f, py8 = 60000.0f;
    const float* cb = out;
    {
        ull big = pack2(1e30f, 1e30f);
#pragma unroll
        for (int g = 0; g < 4; ++g) { px[g] = big; py[g] = big; }
    }
    if (act) {
        int a = cell / NPIX, pos = cell - a*NPIX;
        int jj = pos / NWc, ii = pos - jj*NWc;
        cb = out + ((size_t)(b*NAc + a)*CH)*NPIX + (size_t)pos;
        float fx = (float)ii * SXc, fy = (float)jj * SYc;
        float pxs[Kc], pys[Kc];
#pragma unroll
        for (int k = 0; k < Kc; ++k) {
            float xv = cb[(2*k)*NPIX];
            float yv = cb[(2*k+1)*NPIX];
            if (k == 0) { xv = sigmoidf_(xv); yv = sigmoidf_(yv); }
            pxs[k] = fmaf(xv, SXc, fx);
            pys[k] = fmaf(yv, SYc, fy);
        }
#pragma unroll
        for (int g = 0; g < 4; ++g) {
            px[g] = pack2(pxs[2*g], pxs[2*g+1]);
            py[g] = pack2(pys[2*g], pys[2*g+1]);
        }
        px8 = pxs[8]; py8 = pys[8];
    }

    const ull nTH2 = pack2(-TH2f, -TH2f);
    int nv = snv;
    int npair = (nv + 1) >> 1;   // pairs, padded by dummy target
    int macc = 0;

    // Staged screen, TWO targets per iteration. Stage 1 tests corners 0..5
    // of both targets; pigeonhole: cnt_total >= 6 implies >= 3 among
    // corners 0..5, so acc > -3 for a target proves it cannot trigger.
    // Merged sign counting: 3 prmt + 4 dp4a for 12 corner tests.
#pragma unroll 2
    for (int p = 0; p < npair; ++p) {
        const float* tp0 = &sgt[(2*p)*20];
        const float* tp1 = tp0 + 20;
        const ulonglong2* q = (const ulonglong2*)tp0;
        const ulonglong2* r = (const ulonglong2*)tp1;
        ulonglong2 q0 = q[0], q1 = q[1], q2 = q[2];
        ulonglong2 r0 = r[0], r1 = r[1], r2 = r[2];

        ull dA0 = dist2m(px[0], py[0], q0.x, q0.y, nTH2);
        ull dA1 = dist2m(px[1], py[1], q1.x, q1.y, nTH2);
        ull dA2 = dist2m(px[2], py[2], q2.x, q2.y, nTH2);
        ull dB0 = dist2m(px[0], py[0], r0.x, r0.y, nTH2);
        ull dB1 = dist2m(px[1], py[1], r1.x, r1.y, nTH2);
        ull dB2 = dist2m(px[2], py[2], r2.x, r2.y, nTH2);

        uint pA01 = prmt_sgn4(dA0, dA1);   // A corners 0..3
        uint pMid = prmt_sgn4(dA2, dB0);   // bytes0,1 = A corners 4,5; bytes2,3 = B corners 0,1
        uint pB12 = prmt_sgn4(dB1, dB2);   // B corners 2..5

        int accA = dp4a_sel(pA01, 0x01010101u, dp4a_sel(pMid, 0x00000101u, 0));
        int accB = dp4a_sel(pB12, 0x01010101u, dp4a_sel(pMid, 0x01010000u, 0));

        if (min(accA, accB) <= -3) {
            // Stage 2: complete the 9-corner counts for both targets.
            ulonglong2 q3 = q[3], r3 = r[3];
            ull q4 = *(const ull*)(tp0 + 16);
            ull r4 = *(const ull*)(tp1 + 16);
            ull dA3 = dist2m(px[3], py[3], q3.x, q3.y, nTH2);
            ull dB3 = dist2m(px[3], py[3], r3.x, r3.y, nTH2);

            float ax = px8 + __uint_as_float((uint)q4);
            float ay = py8 + __uint_as_float((uint)(q4 >> 32));
            float dA8 = fmaf(ax, ax, fmaf(ay, ay, -TH2f));
            float bx = px8 + __uint_as_float((uint)r4);
            float by = py8 + __uint_as_float((uint)(r4 >> 32));
            float dB8 = fmaf(bx, bx, fmaf(by, by, -TH2f));

            int fA = dp4a_sel(prmt_sgn(dA3), 0x0101u, accA)
                     - (int)(__float_as_uint(dA8) >> 31);
            int fB = dp4a_sel(prmt_sgn(dB3), 0x0101u, accB)
                     - (int)(__float_as_uint(dB8) >> 31);
            macc = min(macc, min(fA, fB));
        }
    }

    // macc = -(max #corners inside). mean-conf > 0.6 (sum > 5.4) requires
    // >= 6 corners within TH. Cold exact rescan only if any target could
    // pass (per-lane rare).
    float m = 0.0f;
    if (macc <= -6) m = rescan_cell(cb, sgt, cell, nv);

    int doconf = (ep[0] > 15) ? 1 : 0;
    float contrib = 0.0f;
    if (act) {
        int over = (m * (1.0f/(float)Kc)) > SILf;
        int win = -1;
        if (sbm[cell >> 5] & (1u << (cell & 31))) {
            for (int t = nv-1; t >= 0; --t)
                if (scode[t] == cell) { win = t; break; }
        }
        if (win >= 0 || (doconf && !over))
            contrib = cell_loss(cb, b, win, doconf, over, sconft, stcls);
    }

    // warp-shuffle reduction + one atomic per block
#pragma unroll
    for (int off = 16; off > 0; off >>= 1)
        contrib += __shfl_down_sync(0xFFFFFFFFu, contrib, off);
    int lane = tid & 31, wid = tid >> 5;
    if (lane == 0) wred[wid] = contrib;
    __syncthreads();
    if (tid < 8) {
        float v = wred[tid];
#pragma unroll
        for (int off = 4; off > 0; off >>= 1)
            v += __shfl_down_sync(0xFFu, v, off);
        if (tid == 0) atomicAdd(loss, v);
    }
}

extern "C" void kernel_launch(void* const* d_in, const int* in_sizes, int n_in,
                              void* d_out, int out_size)
{
    const float* out = (const float*)d_in[0];
    const float* tgt = (const float*)d_in[1];
    const int*   ep  = (const int*)d_in[2];
    float* loss = (float*)d_out;

    region_prep<<<NBc, 64>>>(out, tgt, loss);
    dim3 g((NANCH + 255)/256, NBc);
    region_main<<<g, 256>>>(out, ep, loss);
}